// round 4
// baseline (speedup 1.0000x reference)
#include <cuda_runtime.h>
#include <cstdint>

// Fully fused quantized CIFAR-10 net, integer/DP4A datapath, vectorized depthwise.
// 2 images per CTA (grid 512 -> single wave on 148 SMs @ 4 CTAs/SM).
// Integer round-half-even everywhere == jnp.round ==> bit-exact vs reference.

#define THREADS 256

// ---------------- packed weight globals (written by prep_kernel) ----------------
__device__ uint32_t gW0[4];      // conv0 [oc<3]: (3 x int8 code, 0)
__device__ uint32_t gPW1[32];    // pw1 [oc]: (3 ic codes, 0)
__device__ uint32_t gPW2[512];   // pw2 [oc*8+g]: 4 ic codes
__device__ uint32_t gPW3[2048];  // pw3 [oc*16+g]: 4 ic codes
__device__ uint32_t gFC1[8192];  // fc1 [g*256+oc]: 4 ic codes (coalesced by oc)
__device__ uint32_t gFC2[640];   // fc2 [oc*64+g]: 4 ic codes
__device__ uint32_t gDW1r[16];   // dw1 row-packed [c*3+ky] = (w0,w1,w2,0), 9 used
__device__ uint32_t gDW2r[96];   // dw2 row-packed [c*3+ky]
__device__ uint32_t gDW3r[192];  // dw3 row-packed [c*3+ky]

// ---------------- helpers ----------------
__device__ __forceinline__ int clampi(int v, int lo, int hi) { return min(max(v, lo), hi); }
__device__ __forceinline__ uint32_t pack4(int a, int b, int c, int d) {
    return (uint32_t)(a & 0xFF) | ((uint32_t)(b & 0xFF) << 8) |
           ((uint32_t)(c & 0xFF) << 16) | ((uint32_t)(d & 0xFF) << 24);
}
__device__ __forceinline__ int qw4c(float w) {
    float q = rintf(w * 4.f); return (int)fmaxf(-8.f, fminf(7.f, q));
}
__device__ __forceinline__ int qw8c(float w) {
    float q = rintf(w * 4.f); return (int)fmaxf(-128.f, fminf(127.f, q));
}
// activation 8-bit input quant code (round-to-nearest-even == jnp.round)
__device__ __forceinline__ int qa8c(float v) {
    return clampi(__float2int_rn(v * 16.f), -128, 127);
}
// round-half-even of S/4 (act4 requant after dw/pw: round(S*0.25))
__device__ __forceinline__ int rq2(int S) {
    int q = S >> 2, r = S & 3; return q + (r > 2) + ((r == 2) & (q & 1));
}
// round-half-even of S/32 (conv0 act4 requant)
__device__ __forceinline__ int rq5(int S) {
    int q = S >> 5, r = S & 31; return q + (r > 16) + ((r == 16) & (q & 1));
}
// QuantReLU4 code from raw accum (o = S*0.125, code = round(o*4) clip [0,15])
__device__ __forceinline__ int reluc(int S) {
    int m = max(S, 0); int k = m >> 1; k += (k & m & 1); return min(k, 15);
}
// relu code (val c*0.25) -> S_ACT4 signed 4-bit code (round(c*0.5) clip 7)
__device__ __forceinline__ int c2a4(int c) {
    int k = c >> 1; k += (k & c & 1); return min(k, 7);
}

// ---------------- prep: quantize + pack weights ----------------
__global__ void prep_kernel(const float* __restrict__ w0,  const float* __restrict__ dw1,
                            const float* __restrict__ pw1, const float* __restrict__ dw2,
                            const float* __restrict__ pw2, const float* __restrict__ dw3,
                            const float* __restrict__ pw3, const float* __restrict__ wc1,
                            const float* __restrict__ wc2)
{
    int t = blockIdx.x * blockDim.x + threadIdx.x;
    int NT = gridDim.x * blockDim.x;
    for (int i = t; i < 3; i += NT)
        gW0[i] = pack4(qw8c(w0[i*3]), qw8c(w0[i*3+1]), qw8c(w0[i*3+2]), 0);
    for (int i = t; i < 32; i += NT)
        gPW1[i] = pack4(qw4c(pw1[i*3]), qw4c(pw1[i*3+1]), qw4c(pw1[i*3+2]), 0);
    for (int i = t; i < 512; i += NT) {
        int oc = i >> 3, g = i & 7; const float* p = pw2 + oc*32 + g*4;
        gPW2[i] = pack4(qw4c(p[0]), qw4c(p[1]), qw4c(p[2]), qw4c(p[3]));
    }
    for (int i = t; i < 2048; i += NT) {
        int oc = i >> 4, g = i & 15; const float* p = pw3 + oc*64 + g*4;
        gPW3[i] = pack4(qw4c(p[0]), qw4c(p[1]), qw4c(p[2]), qw4c(p[3]));
    }
    for (int i = t; i < 8192; i += NT) {
        int g = i >> 8, oc = i & 255; const float* p = wc1 + oc*128 + g*4;
        gFC1[i] = pack4(qw4c(p[0]), qw4c(p[1]), qw4c(p[2]), qw4c(p[3]));
    }
    for (int i = t; i < 640; i += NT) {
        int oc = i / 64, g = i & 63; const float* p = wc2 + oc*256 + g*4;
        gFC2[i] = pack4(qw4c(p[0]), qw4c(p[1]), qw4c(p[2]), qw4c(p[3]));
    }
    for (int i = t; i < 9; i += NT) {
        int c = i / 3, ky = i % 3; const float* p = dw1 + c*9 + ky*3;
        gDW1r[i] = pack4(qw4c(p[0]), qw4c(p[1]), qw4c(p[2]), 0);
    }
    for (int i = t; i < 96; i += NT) {
        int c = i / 3, ky = i % 3; const float* p = dw2 + c*9 + ky*3;
        gDW2r[i] = pack4(qw4c(p[0]), qw4c(p[1]), qw4c(p[2]), 0);
    }
    for (int i = t; i < 192; i += NT) {
        int c = i / 3, ky = i % 3; const float* p = dw3 + c*9 + ky*3;
        gDW3r[i] = pack4(qw4c(p[0]), qw4c(p[1]), qw4c(p[2]), 0);
    }
}

// ---------------- main fused kernel (2 images per CTA) ----------------
// SMEM: per-image 16KB region (img*16384): halves [0,8192) / [8192,16384) alternate.
// Weights at 32768: PW2w(2048) PW3w(8192) PW1w(128) DW1r(48) DW2r(384) DW3r(768).
#define WB 32768
#define SM_BYTES 44336

__global__ __launch_bounds__(THREADS, 4)
void qnet_kernel(const float* __restrict__ x, float* __restrict__ out)
{
    extern __shared__ unsigned char sm[];
    const int tid = threadIdx.x;
    const int b0  = blockIdx.x * 2;

    uint32_t*  PW2w = (uint32_t*)(sm + WB);
    uint32_t*  PW3w = (uint32_t*)(sm + WB + 2048);
    uint32_t*  PW1w = (uint32_t*)(sm + WB + 10240);
    uint32_t*  DW1r = (uint32_t*)(sm + WB + 10368);
    uint32_t*  DW2r = (uint32_t*)(sm + WB + 10416);
    uint32_t*  DW3r = (uint32_t*)(sm + WB + 10800);

    // ---- stage packed weights (L2-hot) ----
    for (int i = tid; i < 512;  i += THREADS) PW2w[i] = gPW2[i];
    for (int i = tid; i < 2048; i += THREADS) PW3w[i] = gPW3[i];
    if (tid < 32)  PW1w[tid] = gPW1[tid];
    if (tid < 9)   DW1r[tid] = gDW1r[tid];
    if (tid < 96)  DW2r[tid] = gDW2r[tid];
    if (tid < 192) DW3r[tid] = gDW3r[tid];

    // ---- input load + 8-bit quant + conv0 (1x1, 3->3) + act4 requant ----
    {
        int w00 = (int)gW0[0], w01 = (int)gW0[1], w02 = (int)gW0[2];
        #pragma unroll
        for (int img = 0; img < 2; img++) {
            signed char* B = (signed char*)(sm + img * 16384);
            const float* xin = x + (size_t)(b0 + img) * 3072;
            #pragma unroll
            for (int k = 0; k < 4; k++) {
                int p = tid + k * 256;
                int a = (int)pack4(qa8c(xin[p]), qa8c(xin[1024 + p]),
                                   qa8c(xin[2048 + p]), 0);
                B[p]        = (signed char)clampi(rq5(__dp4a(a, w00, 0)), -8, 7);
                B[1024 + p] = (signed char)clampi(rq5(__dp4a(a, w01, 0)), -8, 7);
                B[2048 + p] = (signed char)clampi(rq5(__dp4a(a, w02, 0)), -8, 7);
            }
        }
    }
    __syncthreads();

    // ---- dw1: depthwise 3x3, 3ch @32x32. Thread = 1 word (4 px), all 3 ch ----
    #pragma unroll
    for (int img = 0; img < 2; img++) {
        signed char* B  = (signed char*)(sm + img * 16384);
        uint32_t*    P1 = (uint32_t*)(sm + img * 16384 + 8192);
        int y = tid >> 3, wx = tid & 7;
        int res[3][4];
        #pragma unroll
        for (int c = 0; c < 3; c++) {
            int a0 = 0, a1 = 0, a2 = 0, a3 = 0;
            #pragma unroll
            for (int ky = 0; ky < 3; ky++) {
                int yy = y + ky - 1;
                if ((unsigned)yy <= 31u) {
                    const uint32_t* rp = (const uint32_t*)(B + c * 1024 + yy * 32);
                    uint32_t cur  = rp[wx];
                    uint32_t prev = wx ? rp[wx - 1] : 0u;
                    uint32_t nxt  = (wx < 7) ? rp[wx + 1] : 0u;
                    int wv = (int)DW1r[c * 3 + ky];
                    a0 = __dp4a((int)__byte_perm(cur, prev, 0x0107), wv, a0);
                    a1 = __dp4a((int)cur,                            wv, a1);
                    a2 = __dp4a((int)(cur >> 8),                     wv, a2);
                    a3 = __dp4a((int)__byte_perm(cur, nxt, 0x0432),  wv, a3);
                }
            }
            res[c][0] = clampi(rq2(a0), -8, 7);
            res[c][1] = clampi(rq2(a1), -8, 7);
            res[c][2] = clampi(rq2(a2), -8, 7);
            res[c][3] = clampi(rq2(a3), -8, 7);
        }
        uint4 o;
        o.x = pack4(res[0][0], res[1][0], res[2][0], 0);
        o.y = pack4(res[0][1], res[1][1], res[2][1], 0);
        o.z = pack4(res[0][2], res[1][2], res[2][2], 0);
        o.w = pack4(res[0][3], res[1][3], res[2][3], 0);
        *(uint4*)(P1 + y * 32 + wx * 4) = o;
    }
    __syncthreads();

    // ---- pw1 (3->32) + relu + maxpool2 + act4 requant. Thread = 1 pooled px ----
    #pragma unroll
    for (int img = 0; img < 2; img++) {
        const uint32_t* P1 = (const uint32_t*)(sm + img * 16384 + 8192);
        signed char*    D  = (signed char*)(sm + img * 16384);
        int y = tid >> 4, xx = tid & 15;
        int base = (y * 2) * 32 + xx * 2;
        int q0 = (int)P1[base],      q1 = (int)P1[base + 1];
        int q2 = (int)P1[base + 32], q3 = (int)P1[base + 33];
        #pragma unroll
        for (int oc = 0; oc < 32; oc++) {
            int wv = (int)PW1w[oc];
            int s0 = __dp4a(q0, wv, 0), s1 = __dp4a(q1, wv, 0);
            int s2 = __dp4a(q2, wv, 0), s3 = __dp4a(q3, wv, 0);
            int m = max(max(s0, s1), max(s2, s3));
            D[oc * 256 + tid] = (signed char)c2a4(reluc(m));
        }
    }
    __syncthreads();

    // ---- dw2: depthwise 3x3, 32ch @16x16. Item = 1 word (4 px) of 1 ch ----
    #pragma unroll
    for (int img = 0; img < 2; img++) {
        const signed char* D  = (const signed char*)(sm + img * 16384);
        signed char*       P2 = (signed char*)(sm + img * 16384 + 8192);
        #pragma unroll
        for (int k = 0; k < 8; k++) {
            int item = tid + k * 256;
            int c = item >> 6, w = item & 63;
            int y = w >> 2, wx = w & 3;
            const uint32_t* chb = (const uint32_t*)(D + c * 256);
            int a0 = 0, a1 = 0, a2 = 0, a3 = 0;
            #pragma unroll
            for (int ky = 0; ky < 3; ky++) {
                int yy = y + ky - 1;
                if ((unsigned)yy <= 15u) {
                    const uint32_t* rp = chb + yy * 4;
                    uint32_t cur  = rp[wx];
                    uint32_t prev = wx ? rp[wx - 1] : 0u;
                    uint32_t nxt  = (wx < 3) ? rp[wx + 1] : 0u;
                    int wv = (int)DW2r[c * 3 + ky];
                    a0 = __dp4a((int)__byte_perm(cur, prev, 0x0107), wv, a0);
                    a1 = __dp4a((int)cur,                            wv, a1);
                    a2 = __dp4a((int)(cur >> 8),                     wv, a2);
                    a3 = __dp4a((int)__byte_perm(cur, nxt, 0x0432),  wv, a3);
                }
            }
            int g = c >> 2, lane = c & 3;
            int acc[4] = {a0, a1, a2, a3};
            #pragma unroll
            for (int j = 0; j < 4; j++) {
                int ppx = (y >> 1) * 8 + wx * 2 + (j >> 1);
                int member = (y & 1) * 2 + (j & 1);
                P2[(g * 256 + ppx * 4 + member) * 4 + lane] =
                    (signed char)clampi(rq2(acc[j]), -8, 7);
            }
        }
    }
    __syncthreads();

    // ---- pw2 (32->64) + relu + maxpool2 + requant. 4oc x 1 pooled px ----
    #pragma unroll
    for (int img = 0; img < 2; img++) {
        const uint32_t* P2 = (const uint32_t*)(sm + img * 16384 + 8192);
        signed char*    D3 = (signed char*)(sm + img * 16384);
        #pragma unroll
        for (int k = 0; k < 4; k++) {
            int t2 = tid + k * 256;
            int px = t2 & 63, oc0 = (t2 >> 6) * 4;
            int acc[4][4] = {};
            #pragma unroll
            for (int g = 0; g < 8; g++) {
                uint4 a = *(const uint4*)(P2 + g * 256 + px * 4);
                #pragma unroll
                for (int i2 = 0; i2 < 4; i2++) {
                    int wv = (int)PW2w[(oc0 + i2) * 8 + g];
                    acc[i2][0] = __dp4a((int)a.x, wv, acc[i2][0]);
                    acc[i2][1] = __dp4a((int)a.y, wv, acc[i2][1]);
                    acc[i2][2] = __dp4a((int)a.z, wv, acc[i2][2]);
                    acc[i2][3] = __dp4a((int)a.w, wv, acc[i2][3]);
                }
            }
            #pragma unroll
            for (int i2 = 0; i2 < 4; i2++) {
                int m = max(max(acc[i2][0], acc[i2][1]), max(acc[i2][2], acc[i2][3]));
                D3[(oc0 + i2) * 64 + px] = (signed char)c2a4(reluc(m));
            }
        }
    }
    __syncthreads();

    // ---- dw3: depthwise 3x3, 64ch @8x8. Item = 1 word (4 px) of 1 ch ----
    #pragma unroll
    for (int img = 0; img < 2; img++) {
        const signed char* D3 = (const signed char*)(sm + img * 16384);
        signed char*       P3 = (signed char*)(sm + img * 16384 + 8192);
        #pragma unroll
        for (int k = 0; k < 4; k++) {
            int item = tid + k * 256;
            int c = item >> 4, w = item & 15;
            int y = w >> 1, wx = w & 1;
            const uint32_t* chb = (const uint32_t*)(D3 + c * 64);
            int a0 = 0, a1 = 0, a2 = 0, a3 = 0;
            #pragma unroll
            for (int ky = 0; ky < 3; ky++) {
                int yy = y + ky - 1;
                if ((unsigned)yy <= 7u) {
                    const uint32_t* rp = chb + yy * 2;
                    uint32_t cur  = rp[wx];
                    uint32_t prev = wx ? rp[0] : 0u;
                    uint32_t nxt  = wx ? 0u : rp[1];
                    int wv = (int)DW3r[c * 3 + ky];
                    a0 = __dp4a((int)__byte_perm(cur, prev, 0x0107), wv, a0);
                    a1 = __dp4a((int)cur,                            wv, a1);
                    a2 = __dp4a((int)(cur >> 8),                     wv, a2);
                    a3 = __dp4a((int)__byte_perm(cur, nxt, 0x0432),  wv, a3);
                }
            }
            int g = c >> 2, lane = c & 3;
            int p0 = y * 8 + wx * 4;
            int acc[4] = {a0, a1, a2, a3};
            #pragma unroll
            for (int j = 0; j < 4; j++)
                P3[(g * 64 + p0 + j) * 4 + lane] =
                    (signed char)clampi(rq2(acc[j]), -8, 7);
        }
    }
    __syncthreads();

    // ---- pw3 (64->128) + relu codes. 4oc x 4px blocking ----
    #pragma unroll
    for (int img = 0; img < 2; img++) {
        const uint32_t* P3 = (const uint32_t*)(sm + img * 16384 + 8192);
        unsigned char*  K  = (unsigned char*)(sm + img * 16384);
        #pragma unroll
        for (int k = 0; k < 2; k++) {
            int t2 = tid + k * 256;
            int p0 = (t2 & 15) * 4, oc0 = (t2 >> 4) * 4;
            int acc[4][4] = {};
            #pragma unroll
            for (int g = 0; g < 16; g++) {
                uint4 a = *(const uint4*)(P3 + g * 64 + p0);
                #pragma unroll
                for (int i2 = 0; i2 < 4; i2++) {
                    int wv = (int)PW3w[(oc0 + i2) * 16 + g];
                    acc[i2][0] = __dp4a((int)a.x, wv, acc[i2][0]);
                    acc[i2][1] = __dp4a((int)a.y, wv, acc[i2][1]);
                    acc[i2][2] = __dp4a((int)a.z, wv, acc[i2][2]);
                    acc[i2][3] = __dp4a((int)a.w, wv, acc[i2][3]);
                }
            }
            #pragma unroll
            for (int i2 = 0; i2 < 4; i2++)
                #pragma unroll
                for (int j = 0; j < 4; j++)
                    K[(oc0 + i2) * 64 + p0 + j] = (unsigned char)reluc(acc[i2][j]);
        }
    }
    __syncthreads();

    // ---- global maxpool 8x8 (SIMD byte max) + classifier input quant ----
    if (tid < 128) {
        #pragma unroll
        for (int img = 0; img < 2; img++) {
            const uint4* kp = (const uint4*)(sm + img * 16384 + tid * 64);
            unsigned char* Vb = (unsigned char*)(sm + img * 16384 + 8192);
            uint32_t m = 0;
            #pragma unroll
            for (int i = 0; i < 4; i++) {
                uint4 v = kp[i];
                m = __vmaxu4(m, v.x); m = __vmaxu4(m, v.y);
                m = __vmaxu4(m, v.z); m = __vmaxu4(m, v.w);
            }
            int mb = max(max((int)(m & 255), (int)((m >> 8) & 255)),
                         max((int)((m >> 16) & 255), (int)(m >> 24)));
            Vb[tid] = (unsigned char)c2a4(mb);
        }
    }
    __syncthreads();

    // ---- fc1: 128->256, both images share each weight load ----
    {
        const uint32_t* Vw0 = (const uint32_t*)(sm + 8192);
        const uint32_t* Vw1 = (const uint32_t*)(sm + 16384 + 8192);
        unsigned char* V2b0 = (unsigned char*)(sm + 8320);
        unsigned char* V2b1 = (unsigned char*)(sm + 16384 + 8320);
        int S0 = 0, S1 = 0;
        #pragma unroll 8
        for (int g = 0; g < 32; g++) {
            int wv = (int)gFC1[g * 256 + tid];
            S0 = __dp4a((int)Vw0[g], wv, S0);
            S1 = __dp4a((int)Vw1[g], wv, S1);
        }
        V2b0[tid] = (unsigned char)c2a4(reluc(S0));
        V2b1[tid] = (unsigned char)c2a4(reluc(S1));
    }
    __syncthreads();

    // ---- fc2: 256->10 both images, output int8 quant (round(o*16) = 2S) ----
    if (tid < 160) {
        int oc = tid >> 4, l = tid & 15;
        const uint32_t* Vw0 = (const uint32_t*)(sm + 8320);
        const uint32_t* Vw1 = (const uint32_t*)(sm + 16384 + 8320);
        int S0 = 0, S1 = 0;
        #pragma unroll
        for (int k = 0; k < 4; k++) {
            int g = l + k * 16;
            int wv = (int)gFC2[oc * 64 + g];
            S0 = __dp4a((int)Vw0[g], wv, S0);
            S1 = __dp4a((int)Vw1[g], wv, S1);
        }
        #pragma unroll
        for (int off = 8; off; off >>= 1) {
            S0 += __shfl_down_sync(0xffffffffu, S0, off, 16);
            S1 += __shfl_down_sync(0xffffffffu, S1, off, 16);
        }
        if (l == 0) {
            out[(size_t)b0 * 10 + oc]       = (float)clampi(2 * S0, -128, 127) * 0.0625f;
            out[(size_t)(b0 + 1) * 10 + oc] = (float)clampi(2 * S1, -128, 127) * 0.0625f;
        }
    }
}

extern "C" void kernel_launch(void* const* d_in, const int* in_sizes, int n_in,
                              void* d_out, int out_size)
{
    (void)in_sizes; (void)n_in; (void)out_size;
    const float* x   = (const float*)d_in[0];
    const float* w0  = (const float*)d_in[1];
    const float* dw1 = (const float*)d_in[2];
    const float* pw1 = (const float*)d_in[3];
    const float* dw2 = (const float*)d_in[4];
    const float* pw2 = (const float*)d_in[5];
    const float* dw3 = (const float*)d_in[6];
    const float* pw3 = (const float*)d_in[7];
    const float* wc1 = (const float*)d_in[8];
    const float* wc2 = (const float*)d_in[9];
    float* out = (float*)d_out;

    prep_kernel<<<48, THREADS>>>(w0, dw1, pw1, dw2, pw2, dw3, pw3, wc1, wc2);
    qnet_kernel<<<512, THREADS, SM_BYTES>>>(x, out);
}

// round 5
// speedup vs baseline: 1.0090x; 1.0090x over previous
#include <cuda_runtime.h>
#include <cstdint>

// Fully fused quantized CIFAR-10 net, integer/DP4A datapath, vectorized depthwise.
// One CTA per image (grid 1024), 6 CTAs/SM target for 75% occupancy.
// Integer round-half-even everywhere == jnp.round ==> bit-exact vs reference.

#define THREADS 256

// ---------------- packed weight globals (written by prep_kernel) ----------------
__device__ uint32_t gW0[4];      // conv0 [oc<3]: (3 x int8 code, 0)
__device__ uint32_t gPW1[32];    // pw1 [oc]: (3 ic codes, 0)
__device__ uint32_t gPW2[512];   // pw2 [oc*8+g]: 4 ic codes
__device__ uint32_t gPW3[2048];  // pw3 [oc*16+g]: 4 ic codes
__device__ uint32_t gFC1[8192];  // fc1 [g*256+oc]: 4 ic codes (coalesced by oc)
__device__ uint32_t gFC2[640];   // fc2 [oc*64+g]: 4 ic codes
__device__ uint32_t gDW1r[16];   // dw1 row-packed [c*3+ky] = (w0,w1,w2,0), 9 used
__device__ uint32_t gDW2r[96];   // dw2 row-packed [c*3+ky]
__device__ uint32_t gDW3r[192];  // dw3 row-packed [c*3+ky]

// ---------------- helpers ----------------
__device__ __forceinline__ int clampi(int v, int lo, int hi) { return min(max(v, lo), hi); }
__device__ __forceinline__ uint32_t pack4(int a, int b, int c, int d) {
    return (uint32_t)(a & 0xFF) | ((uint32_t)(b & 0xFF) << 8) |
           ((uint32_t)(c & 0xFF) << 16) | ((uint32_t)(d & 0xFF) << 24);
}
__device__ __forceinline__ int qw4c(float w) {
    float q = rintf(w * 4.f); return (int)fmaxf(-8.f, fminf(7.f, q));
}
__device__ __forceinline__ int qw8c(float w) {
    float q = rintf(w * 4.f); return (int)fmaxf(-128.f, fminf(127.f, q));
}
// activation 8-bit input quant code (round-to-nearest-even == jnp.round)
__device__ __forceinline__ int qa8c(float v) {
    return clampi(__float2int_rn(v * 16.f), -128, 127);
}
// round-half-even of S/4 (act4 requant after dw/pw: round(S*0.25))
__device__ __forceinline__ int rq2(int S) {
    int q = S >> 2, r = S & 3; return q + (r > 2) + ((r == 2) & (q & 1));
}
// round-half-even of S/32 (conv0 act4 requant)
__device__ __forceinline__ int rq5(int S) {
    int q = S >> 5, r = S & 31; return q + (r > 16) + ((r == 16) & (q & 1));
}
// QuantReLU4 code from raw accum (o = S*0.125, code = round(o*4) clip [0,15])
__device__ __forceinline__ int reluc(int S) {
    int m = max(S, 0); int k = m >> 1; k += (k & m & 1); return min(k, 15);
}
// relu code (val c*0.25) -> S_ACT4 signed 4-bit code (round(c*0.5) clip 7)
__device__ __forceinline__ int c2a4(int c) {
    int k = c >> 1; k += (k & c & 1); return min(k, 7);
}

// ---------------- prep: quantize + pack weights ----------------
__global__ void prep_kernel(const float* __restrict__ w0,  const float* __restrict__ dw1,
                            const float* __restrict__ pw1, const float* __restrict__ dw2,
                            const float* __restrict__ pw2, const float* __restrict__ dw3,
                            const float* __restrict__ pw3, const float* __restrict__ wc1,
                            const float* __restrict__ wc2)
{
    int t = blockIdx.x * blockDim.x + threadIdx.x;
    int NT = gridDim.x * blockDim.x;
    for (int i = t; i < 3; i += NT)
        gW0[i] = pack4(qw8c(w0[i*3]), qw8c(w0[i*3+1]), qw8c(w0[i*3+2]), 0);
    for (int i = t; i < 32; i += NT)
        gPW1[i] = pack4(qw4c(pw1[i*3]), qw4c(pw1[i*3+1]), qw4c(pw1[i*3+2]), 0);
    for (int i = t; i < 512; i += NT) {
        int oc = i >> 3, g = i & 7; const float* p = pw2 + oc*32 + g*4;
        gPW2[i] = pack4(qw4c(p[0]), qw4c(p[1]), qw4c(p[2]), qw4c(p[3]));
    }
    for (int i = t; i < 2048; i += NT) {
        int oc = i >> 4, g = i & 15; const float* p = pw3 + oc*64 + g*4;
        gPW3[i] = pack4(qw4c(p[0]), qw4c(p[1]), qw4c(p[2]), qw4c(p[3]));
    }
    for (int i = t; i < 8192; i += NT) {
        int g = i >> 8, oc = i & 255; const float* p = wc1 + oc*128 + g*4;
        gFC1[i] = pack4(qw4c(p[0]), qw4c(p[1]), qw4c(p[2]), qw4c(p[3]));
    }
    for (int i = t; i < 640; i += NT) {
        int oc = i / 64, g = i & 63; const float* p = wc2 + oc*256 + g*4;
        gFC2[i] = pack4(qw4c(p[0]), qw4c(p[1]), qw4c(p[2]), qw4c(p[3]));
    }
    for (int i = t; i < 9; i += NT) {
        int c = i / 3, ky = i % 3; const float* p = dw1 + c*9 + ky*3;
        gDW1r[i] = pack4(qw4c(p[0]), qw4c(p[1]), qw4c(p[2]), 0);
    }
    for (int i = t; i < 96; i += NT) {
        int c = i / 3, ky = i % 3; const float* p = dw2 + c*9 + ky*3;
        gDW2r[i] = pack4(qw4c(p[0]), qw4c(p[1]), qw4c(p[2]), 0);
    }
    for (int i = t; i < 192; i += NT) {
        int c = i / 3, ky = i % 3; const float* p = dw3 + c*9 + ky*3;
        gDW3r[i] = pack4(qw4c(p[0]), qw4c(p[1]), qw4c(p[2]), 0);
    }
}

// ---------------- main fused kernel ----------------
// SMEM (27968 B): R0 [0,8192) / R1 [8192,16384) alternate stage buffers.
//  PW2w [16384,18432) PW3w [18432,26624) PW1w [26624,26752)
//  DW1r [26752,26792) DW2r [26792,27176) DW3r [27176,27944)
#define SM_BYTES 27968

__global__ __launch_bounds__(THREADS, 6)
void qnet_kernel(const float* __restrict__ x, float* __restrict__ out)
{
    extern __shared__ unsigned char sm[];
    const int tid = threadIdx.x;
    const int b   = blockIdx.x;

    signed char*   B    = (signed char*)(sm);           // conv0 out [c][1024], x-packed
    uint32_t*      P1   = (uint32_t*)(sm + 8192);       // dw1 out, pixel-packed 3ch words
    signed char*   D    = (signed char*)(sm);           // pw1 out [oc][256], x-packed
    uint32_t*      P2   = (uint32_t*)(sm + 8192);       // dw2 out [g][qidx] 4ch words
    signed char*   D3   = (signed char*)(sm);           // pw2 out [oc][64], x-packed
    uint32_t*      P3   = (uint32_t*)(sm + 8192);       // dw3 out [g][p] 4ch words
    unsigned char* K    = (unsigned char*)(sm);         // pw3 relu codes [oc][64]
    unsigned char* Vb   = (unsigned char*)(sm + 8192);  // 128
    unsigned char* V2b  = (unsigned char*)(sm + 8320);  // 256
    uint32_t*      PW2w = (uint32_t*)(sm + 16384);
    uint32_t*      PW3w = (uint32_t*)(sm + 18432);
    uint32_t*      PW1w = (uint32_t*)(sm + 26624);
    uint32_t*      DW1r = (uint32_t*)(sm + 26752);
    uint32_t*      DW2r = (uint32_t*)(sm + 26792);
    uint32_t*      DW3r = (uint32_t*)(sm + 27176);

    // ---- stage packed weights (L2-hot) ----
    for (int i = tid; i < 512;  i += THREADS) PW2w[i] = gPW2[i];
    for (int i = tid; i < 2048; i += THREADS) PW3w[i] = gPW3[i];
    if (tid < 32)  PW1w[tid] = gPW1[tid];
    if (tid < 9)   DW1r[tid] = gDW1r[tid];
    if (tid < 96)  DW2r[tid] = gDW2r[tid];
    if (tid < 192) DW3r[tid] = gDW3r[tid];

    // ---- input load + 8-bit quant + conv0 (1x1, 3->3) + act4 requant, fused ----
    {
        const float* xin = x + (size_t)b * 3072;
        int w00 = (int)gW0[0], w01 = (int)gW0[1], w02 = (int)gW0[2];
        #pragma unroll
        for (int k = 0; k < 4; k++) {
            int p = tid + k * 256;
            int a = (int)pack4(qa8c(xin[p]), qa8c(xin[1024 + p]), qa8c(xin[2048 + p]), 0);
            B[p]        = (signed char)clampi(rq5(__dp4a(a, w00, 0)), -8, 7);
            B[1024 + p] = (signed char)clampi(rq5(__dp4a(a, w01, 0)), -8, 7);
            B[2048 + p] = (signed char)clampi(rq5(__dp4a(a, w02, 0)), -8, 7);
        }
    }
    __syncthreads();

    // ---- dw1: depthwise 3x3, 3ch @32x32. Thread = 1 word (4 px), all 3 ch ----
    {
        int y = tid >> 3, wx = tid & 7;
        int res[3][4];
        #pragma unroll
        for (int c = 0; c < 3; c++) {
            int a0 = 0, a1 = 0, a2 = 0, a3 = 0;
            #pragma unroll
            for (int ky = 0; ky < 3; ky++) {
                int yy = y + ky - 1;
                if ((unsigned)yy <= 31u) {
                    const uint32_t* rp = (const uint32_t*)(B + c * 1024 + yy * 32);
                    uint32_t cur  = rp[wx];
                    uint32_t prev = wx ? rp[wx - 1] : 0u;
                    uint32_t nxt  = (wx < 7) ? rp[wx + 1] : 0u;
                    int wv = (int)DW1r[c * 3 + ky];
                    a0 = __dp4a((int)__byte_perm(cur, prev, 0x0107), wv, a0);
                    a1 = __dp4a((int)cur,                            wv, a1);
                    a2 = __dp4a((int)(cur >> 8),                     wv, a2);
                    a3 = __dp4a((int)__byte_perm(cur, nxt, 0x0432),  wv, a3);
                }
            }
            res[c][0] = clampi(rq2(a0), -8, 7);
            res[c][1] = clampi(rq2(a1), -8, 7);
            res[c][2] = clampi(rq2(a2), -8, 7);
            res[c][3] = clampi(rq2(a3), -8, 7);
        }
        uint4 o;
        o.x = pack4(res[0][0], res[1][0], res[2][0], 0);
        o.y = pack4(res[0][1], res[1][1], res[2][1], 0);
        o.z = pack4(res[0][2], res[1][2], res[2][2], 0);
        o.w = pack4(res[0][3], res[1][3], res[2][3], 0);
        *(uint4*)(P1 + y * 32 + wx * 4) = o;
    }
    __syncthreads();

    // ---- pw1 (3->32) + relu + maxpool2 + act4 requant. Thread = 1 pooled px ----
    {
        int y = tid >> 4, xx = tid & 15;
        int base = (y * 2) * 32 + xx * 2;
        int q0 = (int)P1[base],      q1 = (int)P1[base + 1];
        int q2 = (int)P1[base + 32], q3 = (int)P1[base + 33];
        #pragma unroll
        for (int oc = 0; oc < 32; oc++) {
            int wv = (int)PW1w[oc];
            int s0 = __dp4a(q0, wv, 0), s1 = __dp4a(q1, wv, 0);
            int s2 = __dp4a(q2, wv, 0), s3 = __dp4a(q3, wv, 0);
            int m = max(max(s0, s1), max(s2, s3));
            D[oc * 256 + tid] = (signed char)c2a4(reluc(m));
        }
    }
    __syncthreads();

    // ---- dw2: depthwise 3x3, 32ch @16x16. Thread-item = 1 word (4 px) of 1 ch ----
    #pragma unroll
    for (int k = 0; k < 8; k++) {
        int item = tid + k * 256;
        int c = item >> 6, w = item & 63;
        int y = w >> 2, wx = w & 3;
        const uint32_t* chb = (const uint32_t*)(D + c * 256);
        int a0 = 0, a1 = 0, a2 = 0, a3 = 0;
        #pragma unroll
        for (int ky = 0; ky < 3; ky++) {
            int yy = y + ky - 1;
            if ((unsigned)yy <= 15u) {
                const uint32_t* rp = chb + yy * 4;
                uint32_t cur  = rp[wx];
                uint32_t prev = wx ? rp[wx - 1] : 0u;
                uint32_t nxt  = (wx < 3) ? rp[wx + 1] : 0u;
                int wv = (int)DW2r[c * 3 + ky];
                a0 = __dp4a((int)__byte_perm(cur, prev, 0x0107), wv, a0);
                a1 = __dp4a((int)cur,                            wv, a1);
                a2 = __dp4a((int)(cur >> 8),                     wv, a2);
                a3 = __dp4a((int)__byte_perm(cur, nxt, 0x0432),  wv, a3);
            }
        }
        int g = c >> 2, lane = c & 3;
        int acc[4] = {a0, a1, a2, a3};
        #pragma unroll
        for (int j = 0; j < 4; j++) {
            int ppx = (y >> 1) * 8 + wx * 2 + (j >> 1);
            int member = (y & 1) * 2 + (j & 1);
            ((signed char*)P2)[(g * 256 + ppx * 4 + member) * 4 + lane] =
                (signed char)clampi(rq2(acc[j]), -8, 7);
        }
    }
    __syncthreads();

    // ---- pw2 (32->64) + relu + maxpool2 + requant. 4oc x 1 pooled px ----
    #pragma unroll
    for (int k = 0; k < 4; k++) {
        int t2 = tid + k * 256;
        int px = t2 & 63, oc0 = (t2 >> 6) * 4;
        int acc[4][4] = {};
        #pragma unroll
        for (int g = 0; g < 8; g++) {
            uint4 a = *(const uint4*)(P2 + g * 256 + px * 4);
            #pragma unroll
            for (int i2 = 0; i2 < 4; i2++) {
                int wv = (int)PW2w[(oc0 + i2) * 8 + g];
                acc[i2][0] = __dp4a((int)a.x, wv, acc[i2][0]);
                acc[i2][1] = __dp4a((int)a.y, wv, acc[i2][1]);
                acc[i2][2] = __dp4a((int)a.z, wv, acc[i2][2]);
                acc[i2][3] = __dp4a((int)a.w, wv, acc[i2][3]);
            }
        }
        #pragma unroll
        for (int i2 = 0; i2 < 4; i2++) {
            int m = max(max(acc[i2][0], acc[i2][1]), max(acc[i2][2], acc[i2][3]));
            D3[(oc0 + i2) * 64 + px] = (signed char)c2a4(reluc(m));
        }
    }
    __syncthreads();

    // ---- dw3: depthwise 3x3, 64ch @8x8. Thread-item = 1 word (4 px) of 1 ch ----
    #pragma unroll
    for (int k = 0; k < 4; k++) {
        int item = tid + k * 256;
        int c = item >> 4, w = item & 15;
        int y = w >> 1, wx = w & 1;
        const uint32_t* chb = (const uint32_t*)(D3 + c * 64);
        int a0 = 0, a1 = 0, a2 = 0, a3 = 0;
        #pragma unroll
        for (int ky = 0; ky < 3; ky++) {
            int yy = y + ky - 1;
            if ((unsigned)yy <= 7u) {
                const uint32_t* rp = chb + yy * 2;
                uint32_t cur  = rp[wx];
                uint32_t prev = wx ? rp[0] : 0u;
                uint32_t nxt  = wx ? 0u : rp[1];
                int wv = (int)DW3r[c * 3 + ky];
                a0 = __dp4a((int)__byte_perm(cur, prev, 0x0107), wv, a0);
                a1 = __dp4a((int)cur,                            wv, a1);
                a2 = __dp4a((int)(cur >> 8),                     wv, a2);
                a3 = __dp4a((int)__byte_perm(cur, nxt, 0x0432),  wv, a3);
            }
        }
        int g = c >> 2, lane = c & 3;
        int p0 = y * 8 + wx * 4;
        int acc[4] = {a0, a1, a2, a3};
        #pragma unroll
        for (int j = 0; j < 4; j++)
            ((signed char*)P3)[(g * 64 + p0 + j) * 4 + lane] =
                (signed char)clampi(rq2(acc[j]), -8, 7);
    }
    __syncthreads();

    // ---- pw3 (64->128) + relu codes. 4oc x 4px blocking ----
    #pragma unroll
    for (int k = 0; k < 2; k++) {
        int t2 = tid + k * 256;
        int p0 = (t2 & 15) * 4, oc0 = (t2 >> 4) * 4;
        int acc[4][4] = {};
        #pragma unroll
        for (int g = 0; g < 16; g++) {
            uint4 a = *(const uint4*)(P3 + g * 64 + p0);
            #pragma unroll
            for (int i2 = 0; i2 < 4; i2++) {
                int wv = (int)PW3w[(oc0 + i2) * 16 + g];
                acc[i2][0] = __dp4a((int)a.x, wv, acc[i2][0]);
                acc[i2][1] = __dp4a((int)a.y, wv, acc[i2][1]);
                acc[i2][2] = __dp4a((int)a.z, wv, acc[i2][2]);
                acc[i2][3] = __dp4a((int)a.w, wv, acc[i2][3]);
            }
        }
        #pragma unroll
        for (int i2 = 0; i2 < 4; i2++)
            #pragma unroll
            for (int j = 0; j < 4; j++)
                K[(oc0 + i2) * 64 + p0 + j] = (unsigned char)reluc(acc[i2][j]);
    }
    __syncthreads();

    // ---- global maxpool 8x8 (SIMD byte max) + classifier input quant ----
    if (tid < 128) {
        const uint4* kp = (const uint4*)(K + tid * 64);
        uint32_t m = 0;
        #pragma unroll
        for (int i = 0; i < 4; i++) {
            uint4 v = kp[i];
            m = __vmaxu4(m, v.x); m = __vmaxu4(m, v.y);
            m = __vmaxu4(m, v.z); m = __vmaxu4(m, v.w);
        }
        int mb = max(max((int)(m & 255), (int)((m >> 8) & 255)),
                     max((int)((m >> 16) & 255), (int)(m >> 24)));
        Vb[tid] = (unsigned char)c2a4(mb);
    }
    __syncthreads();

    // ---- fc1: 128->256 (weights streamed from global, coalesced, L2-hot) ----
    {
        const uint32_t* Vw = (const uint32_t*)Vb;
        int S = 0;
        #pragma unroll 8
        for (int g = 0; g < 32; g++)
            S = __dp4a((int)Vw[g], (int)gFC1[g * 256 + tid], S);
        V2b[tid] = (unsigned char)c2a4(reluc(S));
    }
    __syncthreads();

    // ---- fc2: 256->10, output int8 quant (o = S*0.125 -> round(o*16) = 2S) ----
    if (tid < 160) {
        int oc = tid >> 4, l = tid & 15;
        const uint32_t* Vw = (const uint32_t*)V2b;
        int S = 0;
        #pragma unroll
        for (int k = 0; k < 4; k++) {
            int g = l + k * 16;
            S = __dp4a((int)Vw[g], (int)gFC2[oc * 64 + g], S);
        }
        #pragma unroll
        for (int off = 8; off; off >>= 1) S += __shfl_down_sync(0xffffffffu, S, off, 16);
        if (l == 0) {
            int o = clampi(2 * S, -128, 127);
            out[(size_t)b * 10 + oc] = (float)o * 0.0625f;
        }
    }
}

extern "C" void kernel_launch(void* const* d_in, const int* in_sizes, int n_in,
                              void* d_out, int out_size)
{
    (void)in_sizes; (void)n_in; (void)out_size;
    const float* x   = (const float*)d_in[0];
    const float* w0  = (const float*)d_in[1];
    const float* dw1 = (const float*)d_in[2];
    const float* pw1 = (const float*)d_in[3];
    const float* dw2 = (const float*)d_in[4];
    const float* pw2 = (const float*)d_in[5];
    const float* dw3 = (const float*)d_in[6];
    const float* pw3 = (const float*)d_in[7];
    const float* wc1 = (const float*)d_in[8];
    const float* wc2 = (const float*)d_in[9];
    float* out = (float*)d_out;

    prep_kernel<<<48, THREADS>>>(w0, dw1, pw1, dw2, pw2, dw3, pw3, wc1, wc2);
    qnet_kernel<<<1024, THREADS, SM_BYTES>>>(x, out);
}

// round 6
// speedup vs baseline: 1.1232x; 1.1132x over previous
#include <cuda_runtime.h>
#include <cstdint>

// Fully fused quantized CIFAR-10 net, integer/DP4A datapath, vectorized depthwise.
// One CTA per image (grid 1024, 5 CTAs/SM). Instruction-minimized requant:
// branch-free round-half-even and fused double-quant. Bit-exact vs reference.

#define THREADS 256

// ---------------- packed weight globals (written by prep_kernel) ----------------
__device__ uint32_t gW0[4];      // conv0 [oc<3]: (3 x int8 code, 0)
__device__ uint32_t gPW1[32];    // pw1 [oc]: (3 ic codes, 0)
__device__ uint32_t gPW2[512];   // pw2 [oc*8+g]: 4 ic codes
__device__ uint32_t gPW3[2048];  // pw3 [oc*16+g]: 4 ic codes
__device__ uint32_t gFC1[8192];  // fc1 [g*256+oc]: 4 ic codes (coalesced by oc)
__device__ uint32_t gFC2[640];   // fc2 [oc*64+g]: 4 ic codes
__device__ uint32_t gDW1r[16];   // dw1 row-packed [c*3+ky] = (w0,w1,w2,0), 9 used
__device__ uint32_t gDW2r[96];   // dw2 row-packed [c*3+ky]
__device__ uint32_t gDW3r[192];  // dw3 row-packed [c*3+ky]

// ---------------- helpers ----------------
__device__ __forceinline__ int clampi(int v, int lo, int hi) { return min(max(v, lo), hi); }
__device__ __forceinline__ uint32_t pack4(int a, int b, int c, int d) {
    return (uint32_t)(a & 0xFF) | ((uint32_t)(b & 0xFF) << 8) |
           ((uint32_t)(c & 0xFF) << 16) | ((uint32_t)(d & 0xFF) << 24);
}
__device__ __forceinline__ int qw4c(float w) {
    float q = rintf(w * 4.f); return (int)fmaxf(-8.f, fminf(7.f, q));
}
__device__ __forceinline__ int qw8c(float w) {
    float q = rintf(w * 4.f); return (int)fmaxf(-128.f, fminf(127.f, q));
}
// activation 8-bit input quant code (round-to-nearest-even == jnp.round)
__device__ __forceinline__ int qa8c(float v) {
    return clampi(__float2int_rn(v * 16.f), -128, 127);
}
// branch-free round-half-even of S/4 (all signed S, arithmetic shift)
__device__ __forceinline__ int rq2(int S) {
    return (S + 1 + ((S >> 2) & 1)) >> 2;
}
// branch-free round-half-even of S/32
__device__ __forceinline__ int rq5(int S) {
    return (S + 15 + ((S >> 5) & 1)) >> 5;
}
// fused QuantReLU4 + S_ACT4 requant: c2a4(reluc(S)) == min(rhe(max(S,0)/4), 7)
__device__ __forceinline__ int fq4(int S) {
    int m = max(S, 0);
    return min((m + 1 + ((m >> 2) & 1)) >> 2, 7);
}

// ---------------- prep: quantize + pack weights ----------------
__global__ void prep_kernel(const float* __restrict__ w0,  const float* __restrict__ dw1,
                            const float* __restrict__ pw1, const float* __restrict__ dw2,
                            const float* __restrict__ pw2, const float* __restrict__ dw3,
                            const float* __restrict__ pw3, const float* __restrict__ wc1,
                            const float* __restrict__ wc2)
{
    int t = blockIdx.x * blockDim.x + threadIdx.x;
    int NT = gridDim.x * blockDim.x;
    for (int i = t; i < 3; i += NT)
        gW0[i] = pack4(qw8c(w0[i*3]), qw8c(w0[i*3+1]), qw8c(w0[i*3+2]), 0);
    for (int i = t; i < 32; i += NT)
        gPW1[i] = pack4(qw4c(pw1[i*3]), qw4c(pw1[i*3+1]), qw4c(pw1[i*3+2]), 0);
    for (int i = t; i < 512; i += NT) {
        int oc = i >> 3, g = i & 7; const float* p = pw2 + oc*32 + g*4;
        gPW2[i] = pack4(qw4c(p[0]), qw4c(p[1]), qw4c(p[2]), qw4c(p[3]));
    }
    for (int i = t; i < 2048; i += NT) {
        int oc = i >> 4, g = i & 15; const float* p = pw3 + oc*64 + g*4;
        gPW3[i] = pack4(qw4c(p[0]), qw4c(p[1]), qw4c(p[2]), qw4c(p[3]));
    }
    for (int i = t; i < 8192; i += NT) {
        int g = i >> 8, oc = i & 255; const float* p = wc1 + oc*128 + g*4;
        gFC1[i] = pack4(qw4c(p[0]), qw4c(p[1]), qw4c(p[2]), qw4c(p[3]));
    }
    for (int i = t; i < 640; i += NT) {
        int oc = i / 64, g = i & 63; const float* p = wc2 + oc*256 + g*4;
        gFC2[i] = pack4(qw4c(p[0]), qw4c(p[1]), qw4c(p[2]), qw4c(p[3]));
    }
    for (int i = t; i < 9; i += NT) {
        int c = i / 3, ky = i % 3; const float* p = dw1 + c*9 + ky*3;
        gDW1r[i] = pack4(qw4c(p[0]), qw4c(p[1]), qw4c(p[2]), 0);
    }
    for (int i = t; i < 96; i += NT) {
        int c = i / 3, ky = i % 3; const float* p = dw2 + c*9 + ky*3;
        gDW2r[i] = pack4(qw4c(p[0]), qw4c(p[1]), qw4c(p[2]), 0);
    }
    for (int i = t; i < 192; i += NT) {
        int c = i / 3, ky = i % 3; const float* p = dw3 + c*9 + ky*3;
        gDW3r[i] = pack4(qw4c(p[0]), qw4c(p[1]), qw4c(p[2]), 0);
    }
}

// ---------------- main fused kernel ----------------
// SMEM (27968 B): R0 [0,8192) / R1 [8192,16384) alternate stage buffers.
//  PW2w [16384,18432) PW3w [18432,26624) PW1w [26624,26752)
//  DW1r [26752,26792) DW2r [26792,27176) DW3r [27176,27944)
#define SM_BYTES 27968

__global__ __launch_bounds__(THREADS, 5)
void qnet_kernel(const float* __restrict__ x, float* __restrict__ out)
{
    extern __shared__ unsigned char sm[];
    const int tid = threadIdx.x;
    const int b   = blockIdx.x;

    signed char*   B    = (signed char*)(sm);           // conv0 out [c][1024], x-packed
    uint32_t*      P1   = (uint32_t*)(sm + 8192);       // dw1 out, pixel-packed 3ch words
    signed char*   D    = (signed char*)(sm);           // pw1 out [oc][256], x-packed
    uint32_t*      P2   = (uint32_t*)(sm + 8192);       // dw2 out [g][qidx] 4ch words
    signed char*   D3   = (signed char*)(sm);           // pw2 out [oc][64], x-packed
    uint32_t*      P3   = (uint32_t*)(sm + 8192);       // dw3 out [g][p] 4ch words
    int*           PM   = (int*)(sm);                   // pw3 raw maxima [oc][16] int32
    unsigned char* Vb   = (unsigned char*)(sm + 8192);  // 128
    unsigned char* V2b  = (unsigned char*)(sm + 8320);  // 256
    uint32_t*      PW2w = (uint32_t*)(sm + 16384);
    uint32_t*      PW3w = (uint32_t*)(sm + 18432);
    uint32_t*      PW1w = (uint32_t*)(sm + 26624);
    uint32_t*      DW1r = (uint32_t*)(sm + 26752);
    uint32_t*      DW2r = (uint32_t*)(sm + 26792);
    uint32_t*      DW3r = (uint32_t*)(sm + 27176);

    // ---- stage packed weights (L2-hot) ----
    for (int i = tid; i < 512;  i += THREADS) PW2w[i] = gPW2[i];
    for (int i = tid; i < 2048; i += THREADS) PW3w[i] = gPW3[i];
    if (tid < 32)  PW1w[tid] = gPW1[tid];
    if (tid < 9)   DW1r[tid] = gDW1r[tid];
    if (tid < 96)  DW2r[tid] = gDW2r[tid];
    if (tid < 192) DW3r[tid] = gDW3r[tid];

    // ---- input load (float4) + 8-bit quant + conv0 (1x1, 3->3) + act4 requant ----
    {
        const float4* xv = (const float4*)(x + (size_t)b * 3072);
        float4 v0 = xv[tid];          // channel 0, px 4t..4t+3
        float4 v1 = xv[256 + tid];    // channel 1
        float4 v2 = xv[512 + tid];    // channel 2
        int a0 = (int)pack4(qa8c(v0.x), qa8c(v1.x), qa8c(v2.x), 0);
        int a1 = (int)pack4(qa8c(v0.y), qa8c(v1.y), qa8c(v2.y), 0);
        int a2 = (int)pack4(qa8c(v0.z), qa8c(v1.z), qa8c(v2.z), 0);
        int a3 = (int)pack4(qa8c(v0.w), qa8c(v1.w), qa8c(v2.w), 0);
        #pragma unroll
        for (int oc = 0; oc < 3; oc++) {
            int wv = (int)gW0[oc];
            int c0 = clampi(rq5(__dp4a(a0, wv, 0)), -8, 7);
            int c1 = clampi(rq5(__dp4a(a1, wv, 0)), -8, 7);
            int c2 = clampi(rq5(__dp4a(a2, wv, 0)), -8, 7);
            int c3 = clampi(rq5(__dp4a(a3, wv, 0)), -8, 7);
            ((uint32_t*)B)[oc * 256 + tid] = pack4(c0, c1, c2, c3);
        }
    }
    __syncthreads();

    // ---- dw1: depthwise 3x3, 3ch @32x32. Thread = 1 word (4 px), all 3 ch ----
    {
        int y = tid >> 3, wx = tid & 7;
        int res[3][4];
        #pragma unroll
        for (int c = 0; c < 3; c++) {
            int a0 = 0, a1 = 0, a2 = 0, a3 = 0;
            #pragma unroll
            for (int ky = 0; ky < 3; ky++) {
                int yy = y + ky - 1;
                if ((unsigned)yy <= 31u) {
                    const uint32_t* rp = (const uint32_t*)(B + c * 1024 + yy * 32);
                    uint32_t cur  = rp[wx];
                    uint32_t prev = wx ? rp[wx - 1] : 0u;
                    uint32_t nxt  = (wx < 7) ? rp[wx + 1] : 0u;
                    int wv = (int)DW1r[c * 3 + ky];
                    a0 = __dp4a((int)__byte_perm(cur, prev, 0x0107), wv, a0);
                    a1 = __dp4a((int)cur,                            wv, a1);
                    a2 = __dp4a((int)(cur >> 8),                     wv, a2);
                    a3 = __dp4a((int)__byte_perm(cur, nxt, 0x0432),  wv, a3);
                }
            }
            res[c][0] = clampi(rq2(a0), -8, 7);
            res[c][1] = clampi(rq2(a1), -8, 7);
            res[c][2] = clampi(rq2(a2), -8, 7);
            res[c][3] = clampi(rq2(a3), -8, 7);
        }
        uint4 o;
        o.x = pack4(res[0][0], res[1][0], res[2][0], 0);
        o.y = pack4(res[0][1], res[1][1], res[2][1], 0);
        o.z = pack4(res[0][2], res[1][2], res[2][2], 0);
        o.w = pack4(res[0][3], res[1][3], res[2][3], 0);
        *(uint4*)(P1 + y * 32 + wx * 4) = o;
    }
    __syncthreads();

    // ---- pw1 (3->32) + relu + maxpool2 + act4 requant. Thread = 1 pooled px ----
    {
        int y = tid >> 4, xx = tid & 15;
        int base = (y * 2) * 32 + xx * 2;
        int q0 = (int)P1[base],      q1 = (int)P1[base + 1];
        int q2 = (int)P1[base + 32], q3 = (int)P1[base + 33];
        #pragma unroll
        for (int oc = 0; oc < 32; oc++) {
            int wv = (int)PW1w[oc];
            int s0 = __dp4a(q0, wv, 0), s1 = __dp4a(q1, wv, 0);
            int s2 = __dp4a(q2, wv, 0), s3 = __dp4a(q3, wv, 0);
            int m = max(max(s0, s1), max(s2, s3));
            D[oc * 256 + tid] = (signed char)fq4(m);
        }
    }
    __syncthreads();

    // ---- dw2: depthwise 3x3, 32ch @16x16. Thread-item = 1 word (4 px) of 1 ch ----
    #pragma unroll
    for (int k = 0; k < 8; k++) {
        int item = tid + k * 256;
        int c = item >> 6, w = item & 63;
        int y = w >> 2, wx = w & 3;
        const uint32_t* chb = (const uint32_t*)(D + c * 256);
        int a0 = 0, a1 = 0, a2 = 0, a3 = 0;
        #pragma unroll
        for (int ky = 0; ky < 3; ky++) {
            int yy = y + ky - 1;
            if ((unsigned)yy <= 15u) {
                const uint32_t* rp = chb + yy * 4;
                uint32_t cur  = rp[wx];
                uint32_t prev = wx ? rp[wx - 1] : 0u;
                uint32_t nxt  = (wx < 3) ? rp[wx + 1] : 0u;
                int wv = (int)DW2r[c * 3 + ky];
                a0 = __dp4a((int)__byte_perm(cur, prev, 0x0107), wv, a0);
                a1 = __dp4a((int)cur,                            wv, a1);
                a2 = __dp4a((int)(cur >> 8),                     wv, a2);
                a3 = __dp4a((int)__byte_perm(cur, nxt, 0x0432),  wv, a3);
            }
        }
        int g = c >> 2, lane = c & 3;
        int acc[4] = {a0, a1, a2, a3};
        #pragma unroll
        for (int j = 0; j < 4; j++) {
            int ppx = (y >> 1) * 8 + wx * 2 + (j >> 1);
            int member = (y & 1) * 2 + (j & 1);
            ((signed char*)P2)[(g * 256 + ppx * 4 + member) * 4 + lane] =
                (signed char)clampi(rq2(acc[j]), -8, 7);
        }
    }
    __syncthreads();

    // ---- pw2 (32->64) + relu + maxpool2 + requant. 4oc x 1 pooled px ----
    #pragma unroll
    for (int k = 0; k < 4; k++) {
        int t2 = tid + k * 256;
        int px = t2 & 63, oc0 = (t2 >> 6) * 4;
        int acc[4][4] = {};
        #pragma unroll
        for (int g = 0; g < 8; g++) {
            uint4 a = *(const uint4*)(P2 + g * 256 + px * 4);
            #pragma unroll
            for (int i2 = 0; i2 < 4; i2++) {
                int wv = (int)PW2w[(oc0 + i2) * 8 + g];
                acc[i2][0] = __dp4a((int)a.x, wv, acc[i2][0]);
                acc[i2][1] = __dp4a((int)a.y, wv, acc[i2][1]);
                acc[i2][2] = __dp4a((int)a.z, wv, acc[i2][2]);
                acc[i2][3] = __dp4a((int)a.w, wv, acc[i2][3]);
            }
        }
        #pragma unroll
        for (int i2 = 0; i2 < 4; i2++) {
            int m = max(max(acc[i2][0], acc[i2][1]), max(acc[i2][2], acc[i2][3]));
            D3[(oc0 + i2) * 64 + px] = (signed char)fq4(m);
        }
    }
    __syncthreads();

    // ---- dw3: depthwise 3x3, 64ch @8x8. Thread-item = 1 word (4 px) of 1 ch ----
    #pragma unroll
    for (int k = 0; k < 4; k++) {
        int item = tid + k * 256;
        int c = item >> 4, w = item & 15;
        int y = w >> 1, wx = w & 1;
        const uint32_t* chb = (const uint32_t*)(D3 + c * 64);
        int a0 = 0, a1 = 0, a2 = 0, a3 = 0;
        #pragma unroll
        for (int ky = 0; ky < 3; ky++) {
            int yy = y + ky - 1;
            if ((unsigned)yy <= 7u) {
                const uint32_t* rp = chb + yy * 2;
                uint32_t cur  = rp[wx];
                uint32_t prev = wx ? rp[0] : 0u;
                uint32_t nxt  = wx ? 0u : rp[1];
                int wv = (int)DW3r[c * 3 + ky];
                a0 = __dp4a((int)__byte_perm(cur, prev, 0x0107), wv, a0);
                a1 = __dp4a((int)cur,                            wv, a1);
                a2 = __dp4a((int)(cur >> 8),                     wv, a2);
                a3 = __dp4a((int)__byte_perm(cur, nxt, 0x0432),  wv, a3);
            }
        }
        int g = c >> 2, lane = c & 3;
        int p0 = y * 8 + wx * 4;
        int acc[4] = {a0, a1, a2, a3};
        #pragma unroll
        for (int j = 0; j < 4; j++)
            ((signed char*)P3)[(g * 64 + p0 + j) * 4 + lane] =
                (signed char)clampi(rq2(acc[j]), -8, 7);
    }
    __syncthreads();

    // ---- pw3 (64->128): raw partial maxima only (relu-quant deferred to pool) ----
    #pragma unroll
    for (int k = 0; k < 2; k++) {
        int t2 = tid + k * 256;
        int grp = t2 & 15, p0 = grp * 4, oc0 = (t2 >> 4) * 4;
        int acc[4][4] = {};
        #pragma unroll
        for (int g = 0; g < 16; g++) {
            uint4 a = *(const uint4*)(P3 + g * 64 + p0);
            #pragma unroll
            for (int i2 = 0; i2 < 4; i2++) {
                int wv = (int)PW3w[(oc0 + i2) * 16 + g];
                acc[i2][0] = __dp4a((int)a.x, wv, acc[i2][0]);
                acc[i2][1] = __dp4a((int)a.y, wv, acc[i2][1]);
                acc[i2][2] = __dp4a((int)a.z, wv, acc[i2][2]);
                acc[i2][3] = __dp4a((int)a.w, wv, acc[i2][3]);
            }
        }
        #pragma unroll
        for (int i2 = 0; i2 < 4; i2++)
            PM[(oc0 + i2) * 16 + grp] =
                max(max(acc[i2][0], acc[i2][1]), max(acc[i2][2], acc[i2][3]));
    }
    __syncthreads();

    // ---- global maxpool over raw maxima + fused relu-quant + act4 requant ----
    if (tid < 128) {
        const int* pm = PM + tid * 16;
        int m = pm[0];
        #pragma unroll
        for (int i = 1; i < 16; i++) m = max(m, pm[i]);
        Vb[tid] = (unsigned char)fq4(m);
    }
    __syncthreads();

    // ---- fc1: 128->256 (weights streamed from global, coalesced, L2-hot) ----
    {
        const uint32_t* Vw = (const uint32_t*)Vb;
        int S = 0;
        #pragma unroll 8
        for (int g = 0; g < 32; g++)
            S = __dp4a((int)Vw[g], (int)gFC1[g * 256 + tid], S);
        V2b[tid] = (unsigned char)fq4(S);
    }
    __syncthreads();

    // ---- fc2: 256->10, output int8 quant (o = S*0.125 -> round(o*16) = 2S) ----
    if (tid < 160) {
        int oc = tid >> 4, l = tid & 15;
        const uint32_t* Vw = (const uint32_t*)V2b;
        int S = 0;
        #pragma unroll
        for (int k = 0; k < 4; k++) {
            int g = l + k * 16;
            S = __dp4a((int)Vw[g], (int)gFC2[oc * 64 + g], S);
        }
        #pragma unroll
        for (int off = 8; off; off >>= 1) S += __shfl_down_sync(0xffffffffu, S, off, 16);
        if (l == 0) {
            int o = clampi(2 * S, -128, 127);
            out[(size_t)b * 10 + oc] = (float)o * 0.0625f;
        }
    }
}

extern "C" void kernel_launch(void* const* d_in, const int* in_sizes, int n_in,
                              void* d_out, int out_size)
{
    (void)in_sizes; (void)n_in; (void)out_size;
    const float* x   = (const float*)d_in[0];
    const float* w0  = (const float*)d_in[1];
    const float* dw1 = (const float*)d_in[2];
    const float* pw1 = (const float*)d_in[3];
    const float* dw2 = (const float*)d_in[4];
    const float* pw2 = (const float*)d_in[5];
    const float* dw3 = (const float*)d_in[6];
    const float* pw3 = (const float*)d_in[7];
    const float* wc1 = (const float*)d_in[8];
    const float* wc2 = (const float*)d_in[9];
    float* out = (float*)d_out;

    prep_kernel<<<48, THREADS>>>(w0, dw1, pw1, dw2, pw2, dw3, pw3, wc1, wc2);
    qnet_kernel<<<1024, THREADS, SM_BYTES>>>(x, out);
}